// round 10
// baseline (speedup 1.0000x reference)
#include <cuda_runtime.h>

// 8-point DCT-II basis as compile-time constants -> FFMA immediates after unroll.
__device__ constexpr float D8[8][8] = {
  { 0.35355339059327373f, 0.35355339059327373f, 0.35355339059327373f, 0.35355339059327373f,
    0.35355339059327373f, 0.35355339059327373f, 0.35355339059327373f, 0.35355339059327373f},
  { 0.49039264020161522f, 0.41573480615127262f, 0.27778511650980114f, 0.09754516100806417f,
   -0.09754516100806417f,-0.27778511650980114f,-0.41573480615127262f,-0.49039264020161522f},
  { 0.46193976625564337f, 0.19134171618254492f,-0.19134171618254492f,-0.46193976625564337f,
   -0.46193976625564337f,-0.19134171618254492f, 0.19134171618254492f, 0.46193976625564337f},
  { 0.41573480615127262f,-0.09754516100806417f,-0.49039264020161522f,-0.27778511650980114f,
    0.27778511650980114f, 0.49039264020161522f, 0.09754516100806417f,-0.41573480615127262f},
  { 0.35355339059327379f,-0.35355339059327379f,-0.35355339059327379f, 0.35355339059327379f,
    0.35355339059327379f,-0.35355339059327379f,-0.35355339059327379f, 0.35355339059327379f},
  { 0.27778511650980114f,-0.49039264020161522f, 0.09754516100806417f, 0.41573480615127262f,
   -0.41573480615127262f,-0.09754516100806417f, 0.49039264020161522f,-0.27778511650980114f},
  { 0.19134171618254492f,-0.46193976625564337f, 0.46193976625564337f,-0.19134171618254492f,
   -0.19134171618254492f, 0.46193976625564337f,-0.46193976625564337f, 0.19134171618254492f},
  { 0.09754516100806417f,-0.27778511650980114f, 0.41573480615127262f,-0.49039264020161522f,
    0.49039264020161522f,-0.41573480615127262f, 0.27778511650980114f,-0.09754516100806417f}
};

__constant__ float QYc[64] = {
  16,11,10,16,24,40,51,61,
  12,12,14,19,26,58,60,55,
  14,13,16,24,40,57,69,56,
  14,17,22,29,51,87,80,62,
  18,22,37,56,68,109,103,77,
  24,35,55,64,81,104,113,92,
  49,64,78,87,103,121,120,101,
  72,92,95,98,112,100,103,99
};
__constant__ float QCc[64] = {
  17,18,24,47,99,99,99,99,
  18,21,26,66,99,99,99,99,
  24,26,56,99,99,99,99,99,
  47,66,99,99,99,99,99,99,
  99,99,99,99,99,99,99,99,
  99,99,99,99,99,99,99,99,
  99,99,99,99,99,99,99,99,
  99,99,99,99,99,99,99,99
};

#define QFACTOR 0.5f

// Forward 8-pt DCT with even/odd fold (all 8 outputs). 8 ADD + 32 FMA.
#define DCT_FWD_FOLD(in8, out8)                                            \
  {                                                                        \
    float e_[4], o_[4];                                                    \
    _Pragma("unroll")                                                      \
    for (int j_ = 0; j_ < 4; ++j_) {                                       \
      e_[j_] = in8[j_] + in8[7 - j_];                                      \
      o_[j_] = in8[j_] - in8[7 - j_];                                      \
    }                                                                      \
    _Pragma("unroll")                                                      \
    for (int v_ = 0; v_ < 8; v_ += 2) {                                    \
      float se_ = 0.f, so_ = 0.f;                                          \
      _Pragma("unroll")                                                    \
      for (int j_ = 0; j_ < 4; ++j_) {                                     \
        se_ += D8[v_][j_] * e_[j_];                                        \
        so_ += D8[v_ + 1][j_] * o_[j_];                                    \
      }                                                                    \
      out8[v_] = se_; out8[v_ + 1] = so_;                                  \
    }                                                                      \
  }

// Inverse 8-pt DCT with fold (all 8 outputs). 32 FMA + 8 ADD.
#define DCT_INV_FOLD(w8, rec8)                                             \
  {                                                                        \
    _Pragma("unroll")                                                      \
    for (int j_ = 0; j_ < 4; ++j_) {                                       \
      float E_ = 0.f, O_ = 0.f;                                            \
      _Pragma("unroll")                                                    \
      for (int v_ = 0; v_ < 8; v_ += 2) {                                  \
        E_ += D8[v_][j_] * w8[v_];                                         \
        O_ += D8[v_ + 1][j_] * w8[v_ + 1];                                 \
      }                                                                    \
      rec8[j_] = E_ + O_; rec8[7 - j_] = E_ - O_;                          \
    }                                                                      \
  }

// Forward half: outputs v = B..B+3 from fold arrays e_,o_ into r4. 16 FMA.
#define DCT_FWD4(B, e_, o_, r4)                                            \
  {                                                                        \
    float a0_=0.f,a1_=0.f,a2_=0.f,a3_=0.f;                                 \
    _Pragma("unroll")                                                      \
    for (int j_ = 0; j_ < 4; ++j_) {                                       \
      a0_ += D8[(B)][j_]     * e_[j_];                                     \
      a1_ += D8[(B)+1][j_]   * o_[j_];                                     \
      a2_ += D8[(B)+2][j_]   * e_[j_];                                     \
      a3_ += D8[(B)+3][j_]   * o_[j_];                                     \
    }                                                                      \
    r4[0]=a0_; r4[1]=a1_; r4[2]=a2_; r4[3]=a3_;                            \
  }

// Inverse pair: positions J and 7-J from full coeff array w_. 8 FMA + 2 ADD.
#define DCT_INVPAIR(J, w_, lo_, hi_)                                       \
  {                                                                        \
    float E_=0.f, O_=0.f;                                                  \
    _Pragma("unroll")                                                      \
    for (int v_ = 0; v_ < 8; v_ += 2) {                                    \
      E_ += D8[v_][(J)]   * w_[v_];                                        \
      O_ += D8[v_+1][(J)] * w_[v_+1];                                      \
    }                                                                      \
    lo_ = E_ + O_; hi_ = E_ - O_;                                          \
  }

// Tile: 32 rows x 32 cols, 256 threads. Shared scratch:
//   s  : 24 blocks [blk*72 + x*9 + y]; blk 0..15 Y, 16..19 Cb, 20..23 Cr
//   cfs: 8 chroma ping-pong blocks, same per-block layout
// Stride 9/72 -> conflict-free in both row (stride-1) and column (stride-9)
// orientation. Chroma split stages ping-pong s<->cfs so the two half-threads
// of a unit never read locations the partner is writing.

__global__ __launch_bounds__(256, 8) void diffjpeg_kernel(
    const float* __restrict__ x, float* __restrict__ out)
{
    __shared__ float s[24 * 72];
    __shared__ float cfs[8 * 72];
    __shared__ float2 qYp[64], qCp[64];   // (q, 1/q)

    const int tid = threadIdx.x;
    if (tid < 64) {
        const float a = QYc[tid] * QFACTOR;
        const float b = QCc[tid] * QFACTOR;
        qYp[tid] = make_float2(a, 1.0f / a);
        qCp[tid] = make_float2(b, 1.0f / b);
    }

    const int bz = blockIdx.z;
    const int tr = blockIdx.y;
    const int tc = blockIdx.x;
    const size_t plane4 = 512 * 512 / 4;
    const float4* px4 = (const float4*)x + (size_t)bz * 3 * plane4 + (size_t)(tr * 32) * 128 + tc * 8;
    float4*       po4 = (float4*)out     + (size_t)bz * 3 * plane4 + (size_t)(tr * 32) * 128 + tc * 8;

    const int row = tid >> 3;   // 0..31
    const int cg  = tid & 7;    // 0..7 -> cols 4cg..4cg+3
    const bool hi = (cg & 1);
    const int yblk = (row >> 3) * 4 + (cg >> 1);
    float* bYv = s + yblk * 72 + (row & 7) * 9;

    // ---- Phase 1: load, clip, RGB->YCbCr, Y forward-y DCT (regs+shfl),
    //      chroma 2x2 downsample ----
    {
        const float4 R4 = px4[(size_t)row * 128 + cg];
        const float4 G4 = px4[plane4 + (size_t)row * 128 + cg];
        const float4 B4 = px4[2 * plane4 + (size_t)row * 128 + cg];
        float rr[4] = {R4.x, R4.y, R4.z, R4.w};
        float gg[4] = {G4.x, G4.y, G4.z, G4.w};
        float bb[4] = {B4.x, B4.y, B4.z, B4.w};
        float yv[4], cbv[4], crv[4];
        #pragma unroll
        for (int j = 0; j < 4; ++j) {
            const float r1 = __saturatef(rr[j]) * 255.f;
            const float g1 = __saturatef(gg[j]) * 255.f;
            const float b1 = __saturatef(bb[j]) * 255.f;
            yv[j] = 0.299f * r1 + 0.587f * g1 + 0.114f * b1 - 128.f;
            cbv[j] = -0.168736f * r1 - 0.331264f * g1 + 0.5f * b1;
            crv[j] =  0.5f * r1 - 0.418688f * g1 - 0.081312f * b1;
        }
        float ov[4];
        #pragma unroll
        for (int j = 0; j < 4; ++j) ov[j] = __shfl_xor_sync(0xffffffffu, yv[j], 1);
        float in8[8];
        #pragma unroll
        for (int j = 0; j < 4; ++j) {
            in8[j]     = hi ? ov[j] : yv[j];
            in8[4 + j] = hi ? yv[j] : ov[j];
        }
        float out8[8];
        DCT_FWD_FOLD(in8, out8);
        #pragma unroll
        for (int j = 0; j < 4; ++j)
            bYv[(hi ? 4 : 0) + j] = hi ? out8[4 + j] : out8[j];

        float cbh[2] = {cbv[0] + cbv[1], cbv[2] + cbv[3]};
        float crh[2] = {crv[0] + crv[1], crv[2] + crv[3]};
        #pragma unroll
        for (int k = 0; k < 2; ++k) {
            cbh[k] += __shfl_xor_sync(0xffffffffu, cbh[k], 8);
            crh[k] += __shfl_xor_sync(0xffffffffu, crh[k], 8);
        }
        if ((row & 1) == 0) {
            const int crow = row >> 1;
            const int base = (crow & 7) * 9;
            #pragma unroll
            for (int k = 0; k < 2; ++k) {
                const int ccol = 2 * cg + k;
                const int cblk = 16 + (crow >> 3) * 2 + (ccol >> 3);
                s[cblk * 72 + base + (ccol & 7)]       = 0.25f * cbh[k];
                s[(cblk + 4) * 72 + base + (ccol & 7)] = 0.25f * crh[k];
            }
        }
    }
    __syncthreads();

    // ---- Region 2: Y pass-B on threads 0..127; chroma on 128..255
    //      (2 threads per unit, k = warp-uniform half selector, ping-pong) ----
    if (tid < 128) {
        const int blk = tid >> 3, v = tid & 7;
        float* bp = s + blk * 72 + v;
        float t[8];
        #pragma unroll
        for (int xx = 0; xx < 8; ++xx) t[xx] = bp[xx * 9];
        float cf[8];
        DCT_FWD_FOLD(t, cf);
        #pragma unroll
        for (int u = 0; u < 8; ++u) {
            const float2 qq = qYp[u * 8 + v];
            cf[u] = rintf(cf[u] * qq.y) * qq.x;   // round-half-even
        }
        float w[8];
        DCT_INV_FOLD(cf, w);
        #pragma unroll
        for (int xx = 0; xx < 8; ++xx) bp[xx * 9] = w[xx];
    } else {
        const int t = tid - 128;
        const int k = t >> 6;        // 0/1, uniform per warp-pair
        const int u = t & 63;        // chroma unit 0..63
        const int cblk = u >> 3;     // 0..7 (4 Cb + 4 Cr)
        const int blk = 16 + cblk;
        const int e8 = u & 7;        // row index (a,c) / column index (b)
        float* sB = s + blk * 72;    // chroma block in s
        float* pB = cfs + cblk * 72; // ping-pong block

        // (a) fwd DCT along y: read s rows -> write cfs rows (half outputs)
        {
            const float* rp = sB + e8 * 9;
            float in8[8];
            #pragma unroll
            for (int j = 0; j < 8; ++j) in8[j] = rp[j];
            float e[4], o[4];
            #pragma unroll
            for (int j = 0; j < 4; ++j) { e[j] = in8[j] + in8[7-j]; o[j] = in8[j] - in8[7-j]; }
            float r4[4];
            float* wp = pB + e8 * 9 + k * 4;
            if (k == 0) { DCT_FWD4(0, e, o, r4); }
            else        { DCT_FWD4(4, e, o, r4); }
            wp[0]=r4[0]; wp[1]=r4[1]; wp[2]=r4[2]; wp[3]=r4[3];
        }
        asm volatile("bar.sync 1, 128;" ::: "memory");
        // (b1) fwd DCT along x + quantize: read cfs cols -> write s coeff cols
        {
            const int v = e8;
            const float* cp = pB + v;
            float t8[8];
            #pragma unroll
            for (int xx = 0; xx < 8; ++xx) t8[xx] = cp[xx * 9];
            float e[4], o[4];
            #pragma unroll
            for (int j = 0; j < 4; ++j) { e[j] = t8[j] + t8[7-j]; o[j] = t8[j] - t8[7-j]; }
            float cf4[4];
            if (k == 0) { DCT_FWD4(0, e, o, cf4); }
            else        { DCT_FWD4(4, e, o, cf4); }
            const int uB = k * 4;
            #pragma unroll
            for (int m = 0; m < 4; ++m) {
                const float2 qq = qCp[(uB + m) * 8 + v];
                sB[(uB + m) * 9 + v] = rintf(cf4[m] * qq.y) * qq.x;
            }
        }
        asm volatile("bar.sync 1, 128;" ::: "memory");
        // (b2) inv DCT along x: read s coeff cols -> write cfs cols (pairs)
        {
            const int v = e8;
            float cf[8];
            #pragma unroll
            for (int uu = 0; uu < 8; ++uu) cf[uu] = sB[uu * 9 + v];
            float lo0, hi0, lo1, hi1;
            if (k == 0) {
                DCT_INVPAIR(0, cf, lo0, hi0);
                DCT_INVPAIR(1, cf, lo1, hi1);
                pB[0 * 9 + v] = lo0; pB[7 * 9 + v] = hi0;
                pB[1 * 9 + v] = lo1; pB[6 * 9 + v] = hi1;
            } else {
                DCT_INVPAIR(2, cf, lo0, hi0);
                DCT_INVPAIR(3, cf, lo1, hi1);
                pB[2 * 9 + v] = lo0; pB[5 * 9 + v] = hi0;
                pB[3 * 9 + v] = lo1; pB[4 * 9 + v] = hi1;
            }
        }
        asm volatile("bar.sync 1, 128;" ::: "memory");
        // (c) inv DCT along y: read cfs rows -> write s rows (pairs)
        {
            const float* rp = pB + e8 * 9;
            float w8[8];
            #pragma unroll
            for (int v = 0; v < 8; ++v) w8[v] = rp[v];
            float* wp = sB + e8 * 9;
            float lo0, hi0, lo1, hi1;
            if (k == 0) {
                DCT_INVPAIR(0, w8, lo0, hi0);
                DCT_INVPAIR(1, w8, lo1, hi1);
                wp[0] = lo0; wp[7] = hi0; wp[1] = lo1; wp[6] = hi1;
            } else {
                DCT_INVPAIR(2, w8, lo0, hi0);
                DCT_INVPAIR(3, w8, lo1, hi1);
                wp[2] = lo0; wp[5] = hi0; wp[3] = lo1; wp[4] = hi1;
            }
        }
    }
    __syncthreads();

    // ---- Output: inverse-y for Y in registers + chroma upsample + store ----
    {
        float w[8];
        #pragma unroll
        for (int v = 0; v < 8; ++v) w[v] = bYv[v];
        float E[4], O[4];
        #pragma unroll
        for (int j = 0; j < 4; ++j) {
            float Ee = 0.f, Oo = 0.f;
            #pragma unroll
            for (int v = 0; v < 8; v += 2) {
                Ee += D8[v][j] * w[v];
                Oo += D8[v + 1][j] * w[v + 1];
            }
            E[j] = Ee; O[j] = Oo;
        }
        float yrec[4];
        #pragma unroll
        for (int j = 0; j < 4; ++j)
            yrec[j] = hi ? (E[3 - j] - O[3 - j]) : (E[j] + O[j]);

        const int crow = row >> 1;
        const int base = (crow & 7) * 9;
        const int ccol0 = 2 * cg;
        const int cblk = 16 + (crow >> 3) * 2 + (ccol0 >> 3);
        const float cb0 = s[cblk * 72 + base + (ccol0 & 7)];
        const float cb1 = s[cblk * 72 + base + (ccol0 & 7) + 1];
        const float cr0 = s[(cblk + 4) * 72 + base + (ccol0 & 7)];
        const float cr1 = s[(cblk + 4) * 72 + base + (ccol0 & 7) + 1];
        const float cbm[4] = {cb0, cb0, cb1, cb1};
        const float crm[4] = {cr0, cr0, cr1, cr1};
        float R[4], G[4], B[4];
        #pragma unroll
        for (int j = 0; j < 4; ++j) {
            const float yv = yrec[j] + 128.f;
            R[j] = __saturatef((yv + 1.402f * crm[j]) * (1.0f / 255.0f));
            G[j] = __saturatef((yv - 0.344136f * cbm[j] - 0.714136f * crm[j]) * (1.0f / 255.0f));
            B[j] = __saturatef((yv + 1.772f * cbm[j]) * (1.0f / 255.0f));
        }
        const size_t o = (size_t)row * 128 + cg;
        po4[o]              = make_float4(R[0], R[1], R[2], R[3]);
        po4[plane4 + o]     = make_float4(G[0], G[1], G[2], G[3]);
        po4[2 * plane4 + o] = make_float4(B[0], B[1], B[2], B[3]);
    }
}

extern "C" void kernel_launch(void* const* d_in, const int* in_sizes, int n_in,
                              void* d_out, int out_size)
{
    const float* x = (const float*)d_in[0];
    float* out = (float*)d_out;
    (void)in_sizes; (void)n_in; (void)out_size;
    dim3 grid(16, 16, 16);   // tile cols (512/32), tile rows (512/32), batch
    diffjpeg_kernel<<<grid, 256>>>(x, out);
}

// round 11
// speedup vs baseline: 1.0289x; 1.0289x over previous
#include <cuda_runtime.h>

// 8-point DCT-II basis as compile-time constants -> FFMA immediates after unroll.
__device__ constexpr float D8[8][8] = {
  { 0.35355339059327373f, 0.35355339059327373f, 0.35355339059327373f, 0.35355339059327373f,
    0.35355339059327373f, 0.35355339059327373f, 0.35355339059327373f, 0.35355339059327373f},
  { 0.49039264020161522f, 0.41573480615127262f, 0.27778511650980114f, 0.09754516100806417f,
   -0.09754516100806417f,-0.27778511650980114f,-0.41573480615127262f,-0.49039264020161522f},
  { 0.46193976625564337f, 0.19134171618254492f,-0.19134171618254492f,-0.46193976625564337f,
   -0.46193976625564337f,-0.19134171618254492f, 0.19134171618254492f, 0.46193976625564337f},
  { 0.41573480615127262f,-0.09754516100806417f,-0.49039264020161522f,-0.27778511650980114f,
    0.27778511650980114f, 0.49039264020161522f, 0.09754516100806417f,-0.41573480615127262f},
  { 0.35355339059327379f,-0.35355339059327379f,-0.35355339059327379f, 0.35355339059327379f,
    0.35355339059327379f,-0.35355339059327379f,-0.35355339059327379f, 0.35355339059327379f},
  { 0.27778511650980114f,-0.49039264020161522f, 0.09754516100806417f, 0.41573480615127262f,
   -0.41573480615127262f,-0.09754516100806417f, 0.49039264020161522f,-0.27778511650980114f},
  { 0.19134171618254492f,-0.46193976625564337f, 0.46193976625564337f,-0.19134171618254492f,
   -0.19134171618254492f, 0.46193976625564337f,-0.46193976625564337f, 0.19134171618254492f},
  { 0.09754516100806417f,-0.27778511650980114f, 0.41573480615127262f,-0.49039264020161522f,
    0.49039264020161522f,-0.41573480615127262f, 0.27778511650980114f,-0.09754516100806417f}
};

__constant__ float QYc[64] = {
  16,11,10,16,24,40,51,61,
  12,12,14,19,26,58,60,55,
  14,13,16,24,40,57,69,56,
  14,17,22,29,51,87,80,62,
  18,22,37,56,68,109,103,77,
  24,35,55,64,81,104,113,92,
  49,64,78,87,103,121,120,101,
  72,92,95,98,112,100,103,99
};
__constant__ float QCc[64] = {
  17,18,24,47,99,99,99,99,
  18,21,26,66,99,99,99,99,
  24,26,56,99,99,99,99,99,
  47,66,99,99,99,99,99,99,
  99,99,99,99,99,99,99,99,
  99,99,99,99,99,99,99,99,
  99,99,99,99,99,99,99,99,
  99,99,99,99,99,99,99,99
};

#define QFACTOR 0.5f
// 1024 * D8[0][0]: DC offset equivalent of the per-pixel -128 shift.
#define DC_SHIFT 362.03867196751236f

// Forward 8-pt DCT with even/odd fold (all 8 outputs). 8 ADD + 32 FMA.
#define DCT_FWD_FOLD(in8, out8)                                            \
  {                                                                        \
    float e_[4], o_[4];                                                    \
    _Pragma("unroll")                                                      \
    for (int j_ = 0; j_ < 4; ++j_) {                                       \
      e_[j_] = in8[j_] + in8[7 - j_];                                      \
      o_[j_] = in8[j_] - in8[7 - j_];                                      \
    }                                                                      \
    _Pragma("unroll")                                                      \
    for (int v_ = 0; v_ < 8; v_ += 2) {                                    \
      float se_ = 0.f, so_ = 0.f;                                          \
      _Pragma("unroll")                                                    \
      for (int j_ = 0; j_ < 4; ++j_) {                                     \
        se_ += D8[v_][j_] * e_[j_];                                        \
        so_ += D8[v_ + 1][j_] * o_[j_];                                    \
      }                                                                    \
      out8[v_] = se_; out8[v_ + 1] = so_;                                  \
    }                                                                      \
  }

// Inverse 8-pt DCT with fold (all 8 outputs). 32 FMA + 8 ADD.
#define DCT_INV_FOLD(w8, rec8)                                             \
  {                                                                        \
    _Pragma("unroll")                                                      \
    for (int j_ = 0; j_ < 4; ++j_) {                                       \
      float E_ = 0.f, O_ = 0.f;                                            \
      _Pragma("unroll")                                                    \
      for (int v_ = 0; v_ < 8; v_ += 2) {                                  \
        E_ += D8[v_][j_] * w8[v_];                                         \
        O_ += D8[v_ + 1][j_] * w8[v_ + 1];                                 \
      }                                                                    \
      rec8[j_] = E_ + O_; rec8[7 - j_] = E_ - O_;                          \
    }                                                                      \
  }

// Tile: 32 rows x 32 cols, 256 threads. 24 blocks of 8x8 in shared scratch:
//   blk 0..15 : Y   (blk = (row>>3)*4 + (col>>3))
//   blk 16..19: Cb  (16x16 downsampled), blk 20..23: Cr
// s[blk*72 + x*9 + y]: conflict-free for both access orientations.

__global__ __launch_bounds__(256, 8) void diffjpeg_kernel(
    const float* __restrict__ x, float* __restrict__ out)
{
    __shared__ float s[24 * 72];
    __shared__ float2 qYp[64], qCp[64];   // (q, 1/q)

    const int tid = threadIdx.x;
    if (tid < 64) {
        const float a = QYc[tid] * QFACTOR;
        const float b = QCc[tid] * QFACTOR;
        qYp[tid] = make_float2(a, 1.0f / a);
        qCp[tid] = make_float2(b, 1.0f / b);
    }

    const int bz = blockIdx.z;
    const int tr = blockIdx.y;
    const int tc = blockIdx.x;
    const size_t plane4 = 512 * 512 / 4;
    const float4* px4 = (const float4*)x + (size_t)bz * 3 * plane4 + (size_t)(tr * 32) * 128 + tc * 8;
    float4*       po4 = (float4*)out     + (size_t)bz * 3 * plane4 + (size_t)(tr * 32) * 128 + tc * 8;

    const int row = tid >> 3;   // 0..31
    const int cg  = tid & 7;    // 0..7 -> cols 4cg..4cg+3
    const bool hi = (cg & 1);
    const int yblk = (row >> 3) * 4 + (cg >> 1);
    float* bYv = s + yblk * 72 + (row & 7) * 9;

    // ---- Phase 1: load, clip, RGB->YCbCr (folded identity), Y forward-y
    //      DCT (regs+shfl, DC-shift trick), chroma 2x2 downsample ----
    {
        const float4 R4 = px4[(size_t)row * 128 + cg];
        const float4 G4 = px4[plane4 + (size_t)row * 128 + cg];
        const float4 B4 = px4[2 * plane4 + (size_t)row * 128 + cg];
        float rr[4] = {R4.x, R4.y, R4.z, R4.w};
        float gg[4] = {G4.x, G4.y, G4.z, G4.w};
        float bb[4] = {B4.x, B4.y, B4.z, B4.w};
        float yv[4];
        float cbh[2] = {0.f, 0.f}, crh[2] = {0.f, 0.f};
        #pragma unroll
        for (int j = 0; j < 4; ++j) {
            const float r1 = __saturatef(rr[j]);
            const float g1 = __saturatef(gg[j]);
            const float b1 = __saturatef(bb[j]);
            // y in 0..255 scale (no -128; DC-shift applied in freq domain)
            const float y = 76.245f * r1 + 149.685f * g1 + 29.07f * b1;
            yv[j] = y;
            cbh[j >> 1] += fmaf(b1, 255.f, -y);   // (B255 - Y)
            crh[j >> 1] += fmaf(r1, 255.f, -y);   // (R255 - Y)
        }
        // gather the full 8-pixel block row: partner is lane^1 (same row, cg^1)
        float ov[4];
        #pragma unroll
        for (int j = 0; j < 4; ++j) ov[j] = __shfl_xor_sync(0xffffffffu, yv[j], 1);
        float in8[8];
        #pragma unroll
        for (int j = 0; j < 4; ++j) {
            in8[j]     = hi ? ov[j] : yv[j];
            in8[4 + j] = hi ? yv[j] : ov[j];
        }
        float out8[8];
        DCT_FWD_FOLD(in8, out8);
        out8[0] -= DC_SHIFT;   // equivalent of -128 per pixel (v=0 only)
        #pragma unroll
        for (int j = 0; j < 4; ++j)
            bYv[(hi ? 4 : 0) + j] = hi ? out8[4 + j] : out8[j];

        // chroma vertical pair: rows r, r^1 are lanes tid, tid^8 (same warp)
        #pragma unroll
        for (int k = 0; k < 2; ++k) {
            cbh[k] += __shfl_xor_sync(0xffffffffu, cbh[k], 8);
            crh[k] += __shfl_xor_sync(0xffffffffu, crh[k], 8);
        }
        if ((row & 1) == 0) {
            const int crow = row >> 1;
            const int base = (crow & 7) * 9;
            #pragma unroll
            for (int k = 0; k < 2; ++k) {
                const int ccol = 2 * cg + k;
                const int cblk = 16 + (crow >> 3) * 2 + (ccol >> 3);
                // 0.25 (avg) * 0.5643341 / 0.7132668 (color identity scale)
                s[cblk * 72 + base + (ccol & 7)]       = 0.14108352144469527f * cbh[k];
                s[(cblk + 4) * 72 + base + (ccol & 7)] = 0.17831669044222540f * crh[k];
            }
        }
    }
    __syncthreads();

    // ---- Region 2: Y pass-B on threads 0..127; chroma chain on 128..255 ----
    if (tid < 128) {
        const int blk = tid >> 3, v = tid & 7;
        float* bp = s + blk * 72 + v;
        float t[8];
        #pragma unroll
        for (int xx = 0; xx < 8; ++xx) t[xx] = bp[xx * 9];
        float cf[8];
        DCT_FWD_FOLD(t, cf);
        #pragma unroll
        for (int u = 0; u < 8; ++u) {
            const float2 qq = qYp[u * 8 + v];
            cf[u] = rintf(cf[u] * qq.y) * qq.x;   // round-half-even
        }
        float w[8];
        DCT_INV_FOLD(cf, w);
        #pragma unroll
        for (int xx = 0; xx < 8; ++xx) bp[xx * 9] = w[xx];
    } else {
        const int u = tid - 128;   // chroma = 8 blocks x 8 = 64 units
        // (a) chroma forward DCT along y (stride-1 rows)
        if (u < 64) {
            const int blk = 16 + (u >> 3), xx = u & 7;
            float* bp = s + blk * 72 + xx * 9;
            float in8[8];
            #pragma unroll
            for (int j = 0; j < 8; ++j) in8[j] = bp[j];
            float out8[8];
            DCT_FWD_FOLD(in8, out8);
            #pragma unroll
            for (int j = 0; j < 8; ++j) bp[j] = out8[j];
        }
        asm volatile("bar.sync 1, 128;" ::: "memory");
        // (b) chroma vertical passB + quantize (stride-9 columns)
        if (u < 64) {
            const int blk = 16 + (u >> 3), v = u & 7;
            float* bp = s + blk * 72 + v;
            float t[8];
            #pragma unroll
            for (int xx = 0; xx < 8; ++xx) t[xx] = bp[xx * 9];
            float cf[8];
            DCT_FWD_FOLD(t, cf);
            #pragma unroll
            for (int uu = 0; uu < 8; ++uu) {
                const float2 qq = qCp[uu * 8 + v];
                cf[uu] = rintf(cf[uu] * qq.y) * qq.x;
            }
            float w[8];
            DCT_INV_FOLD(cf, w);
            #pragma unroll
            for (int xx = 0; xx < 8; ++xx) bp[xx * 9] = w[xx];
        }
        asm volatile("bar.sync 1, 128;" ::: "memory");
        // (c) chroma inverse DCT along y (rows)
        if (u < 64) {
            const int blk = 16 + (u >> 3), xx = u & 7;
            float* bp = s + blk * 72 + xx * 9;
            float w[8];
            #pragma unroll
            for (int v = 0; v < 8; ++v) w[v] = bp[v];
            float rec[8];
            DCT_INV_FOLD(w, rec);
            #pragma unroll
            for (int j = 0; j < 8; ++j) bp[j] = rec[j];
        }
    }
    __syncthreads();

    // ---- Output: inverse-y for Y in registers (DC-shift restores +128)
    //      + chroma upsample + store ----
    {
        float w[8];
        #pragma unroll
        for (int v = 0; v < 8; ++v) w[v] = bYv[v];
        w[0] += DC_SHIFT;   // adds +128 to every reconstructed pixel
        float E[4], O[4];
        #pragma unroll
        for (int j = 0; j < 4; ++j) {
            float Ee = 0.f, Oo = 0.f;
            #pragma unroll
            for (int v = 0; v < 8; v += 2) {
                Ee += D8[v][j] * w[v];
                Oo += D8[v + 1][j] * w[v + 1];
            }
            E[j] = Ee; O[j] = Oo;
        }
        float yrec[4];
        #pragma unroll
        for (int j = 0; j < 4; ++j)
            yrec[j] = hi ? (E[3 - j] - O[3 - j]) : (E[j] + O[j]);

        const int crow = row >> 1;
        const int base = (crow & 7) * 9;
        const int ccol0 = 2 * cg;
        const int cblk = 16 + (crow >> 3) * 2 + (ccol0 >> 3);
        const float cb0 = s[cblk * 72 + base + (ccol0 & 7)];
        const float cb1 = s[cblk * 72 + base + (ccol0 & 7) + 1];
        const float cr0 = s[(cblk + 4) * 72 + base + (ccol0 & 7)];
        const float cr1 = s[(cblk + 4) * 72 + base + (ccol0 & 7) + 1];
        const float cbm[4] = {cb0, cb0, cb1, cb1};
        const float crm[4] = {cr0, cr0, cr1, cr1};
        float R[4], G[4], B[4];
        #pragma unroll
        for (int j = 0; j < 4; ++j) {
            const float yv = yrec[j];
            R[j] = __saturatef((yv + 1.402f * crm[j]) * (1.0f / 255.0f));
            G[j] = __saturatef((yv - 0.344136f * cbm[j] - 0.714136f * crm[j]) * (1.0f / 255.0f));
            B[j] = __saturatef((yv + 1.772f * cbm[j]) * (1.0f / 255.0f));
        }
        const size_t o = (size_t)row * 128 + cg;
        po4[o]              = make_float4(R[0], R[1], R[2], R[3]);
        po4[plane4 + o]     = make_float4(G[0], G[1], G[2], G[3]);
        po4[2 * plane4 + o] = make_float4(B[0], B[1], B[2], B[3]);
    }
}

extern "C" void kernel_launch(void* const* d_in, const int* in_sizes, int n_in,
                              void* d_out, int out_size)
{
    const float* x = (const float*)d_in[0];
    float* out = (float*)d_out;
    (void)in_sizes; (void)n_in; (void)out_size;
    dim3 grid(16, 16, 16);   // tile cols (512/32), tile rows (512/32), batch
    diffjpeg_kernel<<<grid, 256>>>(x, out);
}

// round 12
// speedup vs baseline: 1.0625x; 1.0327x over previous
#include <cuda_runtime.h>

// 8-point DCT-II basis as compile-time constants -> FFMA immediates after unroll.
__device__ constexpr float D8[8][8] = {
  { 0.35355339059327373f, 0.35355339059327373f, 0.35355339059327373f, 0.35355339059327373f,
    0.35355339059327373f, 0.35355339059327373f, 0.35355339059327373f, 0.35355339059327373f},
  { 0.49039264020161522f, 0.41573480615127262f, 0.27778511650980114f, 0.09754516100806417f,
   -0.09754516100806417f,-0.27778511650980114f,-0.41573480615127262f,-0.49039264020161522f},
  { 0.46193976625564337f, 0.19134171618254492f,-0.19134171618254492f,-0.46193976625564337f,
   -0.46193976625564337f,-0.19134171618254492f, 0.19134171618254492f, 0.46193976625564337f},
  { 0.41573480615127262f,-0.09754516100806417f,-0.49039264020161522f,-0.27778511650980114f,
    0.27778511650980114f, 0.49039264020161522f, 0.09754516100806417f,-0.41573480615127262f},
  { 0.35355339059327379f,-0.35355339059327379f,-0.35355339059327379f, 0.35355339059327379f,
    0.35355339059327379f,-0.35355339059327379f,-0.35355339059327379f, 0.35355339059327379f},
  { 0.27778511650980114f,-0.49039264020161522f, 0.09754516100806417f, 0.41573480615127262f,
   -0.41573480615127262f,-0.09754516100806417f, 0.49039264020161522f,-0.27778511650980114f},
  { 0.19134171618254492f,-0.46193976625564337f, 0.46193976625564337f,-0.19134171618254492f,
   -0.19134171618254492f, 0.46193976625564337f,-0.46193976625564337f, 0.19134171618254492f},
  { 0.09754516100806417f,-0.27778511650980114f, 0.41573480615127262f,-0.49039264020161522f,
    0.49039264020161522f,-0.41573480615127262f, 0.27778511650980114f,-0.09754516100806417f}
};

__constant__ float QYc[64] = {
  16,11,10,16,24,40,51,61,
  12,12,14,19,26,58,60,55,
  14,13,16,24,40,57,69,56,
  14,17,22,29,51,87,80,62,
  18,22,37,56,68,109,103,77,
  24,35,55,64,81,104,113,92,
  49,64,78,87,103,121,120,101,
  72,92,95,98,112,100,103,99
};
__constant__ float QCc[64] = {
  17,18,24,47,99,99,99,99,
  18,21,26,66,99,99,99,99,
  24,26,56,99,99,99,99,99,
  47,66,99,99,99,99,99,99,
  99,99,99,99,99,99,99,99,
  99,99,99,99,99,99,99,99,
  99,99,99,99,99,99,99,99,
  99,99,99,99,99,99,99,99
};

#define QFACTOR 0.5f
// 1024 * D8[0][0]: DC offset equivalent of the per-pixel -128 shift.
#define DC_SHIFT 362.03867196751236f

// Forward 8-pt DCT with even/odd fold (all 8 outputs). 8 ADD + 32 FMA.
#define DCT_FWD_FOLD(in8, out8)                                            \
  {                                                                        \
    float e_[4], o_[4];                                                    \
    _Pragma("unroll")                                                      \
    for (int j_ = 0; j_ < 4; ++j_) {                                       \
      e_[j_] = in8[j_] + in8[7 - j_];                                      \
      o_[j_] = in8[j_] - in8[7 - j_];                                      \
    }                                                                      \
    _Pragma("unroll")                                                      \
    for (int v_ = 0; v_ < 8; v_ += 2) {                                    \
      float se_ = 0.f, so_ = 0.f;                                          \
      _Pragma("unroll")                                                    \
      for (int j_ = 0; j_ < 4; ++j_) {                                     \
        se_ += D8[v_][j_] * e_[j_];                                        \
        so_ += D8[v_ + 1][j_] * o_[j_];                                    \
      }                                                                    \
      out8[v_] = se_; out8[v_ + 1] = so_;                                  \
    }                                                                      \
  }

// Inverse 8-pt DCT with fold (all 8 outputs). 32 FMA + 8 ADD.
#define DCT_INV_FOLD(w8, rec8)                                             \
  {                                                                        \
    _Pragma("unroll")                                                      \
    for (int j_ = 0; j_ < 4; ++j_) {                                       \
      float E_ = 0.f, O_ = 0.f;                                            \
      _Pragma("unroll")                                                    \
      for (int v_ = 0; v_ < 8; v_ += 2) {                                  \
        E_ += D8[v_][j_] * w8[v_];                                         \
        O_ += D8[v_ + 1][j_] * w8[v_ + 1];                                 \
      }                                                                    \
      rec8[j_] = E_ + O_; rec8[7 - j_] = E_ - O_;                          \
    }                                                                      \
  }

// Tile: 32 rows x 32 cols, 256 threads, TWO tiles per CTA (sequential).
// 24 blocks of 8x8 in shared scratch:
//   blk 0..15 : Y   (blk = (row>>3)*4 + (col>>3))
//   blk 16..19: Cb  (16x16 downsampled), blk 20..23: Cr
// s[blk*72 + x*9 + y]: conflict-free for both access orientations.

__global__ __launch_bounds__(256, 8) void diffjpeg_kernel(
    const float* __restrict__ x, float* __restrict__ out)
{
    __shared__ float s[24 * 72];
    __shared__ float2 qYp[64], qCp[64];   // (q, 1/q)

    const int tid = threadIdx.x;
    if (tid < 64) {
        const float a = QYc[tid] * QFACTOR;
        const float b = QCc[tid] * QFACTOR;
        qYp[tid] = make_float2(a, 1.0f / a);
        qCp[tid] = make_float2(b, 1.0f / b);
    }

    const int bz = blockIdx.z;
    const int tr = blockIdx.y;
    const size_t plane4 = 512 * 512 / 4;
    const float4* pbase = (const float4*)x + (size_t)bz * 3 * plane4 + (size_t)(tr * 32) * 128;
    float4*       obase = (float4*)out     + (size_t)bz * 3 * plane4 + (size_t)(tr * 32) * 128;

    const int row = tid >> 3;   // 0..31
    const int cg  = tid & 7;    // 0..7 -> cols 4cg..4cg+3
    const bool hi = (cg & 1);
    const int yblk = (row >> 3) * 4 + (cg >> 1);
    float* bYv = s + yblk * 72 + (row & 7) * 9;

    #pragma unroll 1
    for (int it = 0; it < 2; ++it) {
        const int tcc = blockIdx.x * 2 + it;       // tile col 0..15
        const float4* px4 = pbase + tcc * 8;
        float4*       po4 = obase + tcc * 8;
        if (it) __syncthreads();   // output phase of prev tile read s

        // ---- Phase 1: load, clip, RGB->YCbCr (folded identity), Y forward-y
        //      DCT (regs+shfl, DC-shift trick), chroma 2x2 downsample ----
        {
            const float4 R4 = px4[(size_t)row * 128 + cg];
            const float4 G4 = px4[plane4 + (size_t)row * 128 + cg];
            const float4 B4 = px4[2 * plane4 + (size_t)row * 128 + cg];
            float rr[4] = {R4.x, R4.y, R4.z, R4.w};
            float gg[4] = {G4.x, G4.y, G4.z, G4.w};
            float bb[4] = {B4.x, B4.y, B4.z, B4.w};
            float yv[4];
            float cbh[2] = {0.f, 0.f}, crh[2] = {0.f, 0.f};
            #pragma unroll
            for (int j = 0; j < 4; ++j) {
                const float r1 = __saturatef(rr[j]);
                const float g1 = __saturatef(gg[j]);
                const float b1 = __saturatef(bb[j]);
                const float y = 76.245f * r1 + 149.685f * g1 + 29.07f * b1;
                yv[j] = y;
                cbh[j >> 1] += fmaf(b1, 255.f, -y);   // (B255 - Y)
                crh[j >> 1] += fmaf(r1, 255.f, -y);   // (R255 - Y)
            }
            float ov[4];
            #pragma unroll
            for (int j = 0; j < 4; ++j) ov[j] = __shfl_xor_sync(0xffffffffu, yv[j], 1);
            float in8[8];
            #pragma unroll
            for (int j = 0; j < 4; ++j) {
                in8[j]     = hi ? ov[j] : yv[j];
                in8[4 + j] = hi ? yv[j] : ov[j];
            }
            float out8[8];
            DCT_FWD_FOLD(in8, out8);
            out8[0] -= DC_SHIFT;   // equivalent of -128 per pixel (v=0 only)
            #pragma unroll
            for (int j = 0; j < 4; ++j)
                bYv[(hi ? 4 : 0) + j] = hi ? out8[4 + j] : out8[j];

            #pragma unroll
            for (int k = 0; k < 2; ++k) {
                cbh[k] += __shfl_xor_sync(0xffffffffu, cbh[k], 8);
                crh[k] += __shfl_xor_sync(0xffffffffu, crh[k], 8);
            }
            if ((row & 1) == 0) {
                const int crow = row >> 1;
                const int base = (crow & 7) * 9;
                #pragma unroll
                for (int k = 0; k < 2; ++k) {
                    const int ccol = 2 * cg + k;
                    const int cblk = 16 + (crow >> 3) * 2 + (ccol >> 3);
                    // 0.25 (avg) * 0.5643341 / 0.7132668 (color identity)
                    s[cblk * 72 + base + (ccol & 7)]       = 0.14108352144469527f * cbh[k];
                    s[(cblk + 4) * 72 + base + (ccol & 7)] = 0.17831669044222540f * crh[k];
                }
            }
        }
        __syncthreads();

        // ---- Region 2: Y pass-B on threads 0..127; chroma chain on 128..255 ----
        if (tid < 128) {
            const int blk = tid >> 3, v = tid & 7;
            float* bp = s + blk * 72 + v;
            float t[8];
            #pragma unroll
            for (int xx = 0; xx < 8; ++xx) t[xx] = bp[xx * 9];
            float cf[8];
            DCT_FWD_FOLD(t, cf);
            #pragma unroll
            for (int u = 0; u < 8; ++u) {
                const float2 qq = qYp[u * 8 + v];
                cf[u] = rintf(cf[u] * qq.y) * qq.x;   // round-half-even
            }
            float w[8];
            DCT_INV_FOLD(cf, w);
            #pragma unroll
            for (int xx = 0; xx < 8; ++xx) bp[xx * 9] = w[xx];
        } else {
            const int u = tid - 128;   // chroma = 8 blocks x 8 = 64 units
            if (u < 64) {
                const int blk = 16 + (u >> 3), xx = u & 7;
                float* bp = s + blk * 72 + xx * 9;
                float in8[8];
                #pragma unroll
                for (int j = 0; j < 8; ++j) in8[j] = bp[j];
                float out8[8];
                DCT_FWD_FOLD(in8, out8);
                #pragma unroll
                for (int j = 0; j < 8; ++j) bp[j] = out8[j];
            }
            asm volatile("bar.sync 1, 128;" ::: "memory");
            if (u < 64) {
                const int blk = 16 + (u >> 3), v = u & 7;
                float* bp = s + blk * 72 + v;
                float t[8];
                #pragma unroll
                for (int xx = 0; xx < 8; ++xx) t[xx] = bp[xx * 9];
                float cf[8];
                DCT_FWD_FOLD(t, cf);
                #pragma unroll
                for (int uu = 0; uu < 8; ++uu) {
                    const float2 qq = qCp[uu * 8 + v];
                    cf[uu] = rintf(cf[uu] * qq.y) * qq.x;
                }
                float w[8];
                DCT_INV_FOLD(cf, w);
                #pragma unroll
                for (int xx = 0; xx < 8; ++xx) bp[xx * 9] = w[xx];
            }
            asm volatile("bar.sync 1, 128;" ::: "memory");
            if (u < 64) {
                const int blk = 16 + (u >> 3), xx = u & 7;
                float* bp = s + blk * 72 + xx * 9;
                float w[8];
                #pragma unroll
                for (int v = 0; v < 8; ++v) w[v] = bp[v];
                float rec[8];
                DCT_INV_FOLD(w, rec);
                #pragma unroll
                for (int j = 0; j < 8; ++j) bp[j] = rec[j];
            }
        }
        __syncthreads();

        // ---- Output: inverse-y for Y in registers (DC-shift restores +128)
        //      + chroma upsample + store ----
        {
            float w[8];
            #pragma unroll
            for (int v = 0; v < 8; ++v) w[v] = bYv[v];
            w[0] += DC_SHIFT;   // adds +128 to every reconstructed pixel
            float E[4], O[4];
            #pragma unroll
            for (int j = 0; j < 4; ++j) {
                float Ee = 0.f, Oo = 0.f;
                #pragma unroll
                for (int v = 0; v < 8; v += 2) {
                    Ee += D8[v][j] * w[v];
                    Oo += D8[v + 1][j] * w[v + 1];
                }
                E[j] = Ee; O[j] = Oo;
            }
            float yrec[4];
            #pragma unroll
            for (int j = 0; j < 4; ++j)
                yrec[j] = hi ? (E[3 - j] - O[3 - j]) : (E[j] + O[j]);

            const int crow = row >> 1;
            const int base = (crow & 7) * 9;
            const int ccol0 = 2 * cg;
            const int cblk = 16 + (crow >> 3) * 2 + (ccol0 >> 3);
            const float cb0 = s[cblk * 72 + base + (ccol0 & 7)];
            const float cb1 = s[cblk * 72 + base + (ccol0 & 7) + 1];
            const float cr0 = s[(cblk + 4) * 72 + base + (ccol0 & 7)];
            const float cr1 = s[(cblk + 4) * 72 + base + (ccol0 & 7) + 1];
            const float cbm[4] = {cb0, cb0, cb1, cb1};
            const float crm[4] = {cr0, cr0, cr1, cr1};
            float R[4], G[4], B[4];
            #pragma unroll
            for (int j = 0; j < 4; ++j) {
                const float yv = yrec[j];
                R[j] = __saturatef((yv + 1.402f * crm[j]) * (1.0f / 255.0f));
                G[j] = __saturatef((yv - 0.344136f * cbm[j] - 0.714136f * crm[j]) * (1.0f / 255.0f));
                B[j] = __saturatef((yv + 1.772f * cbm[j]) * (1.0f / 255.0f));
            }
            const size_t o = (size_t)row * 128 + cg;
            po4[o]              = make_float4(R[0], R[1], R[2], R[3]);
            po4[plane4 + o]     = make_float4(G[0], G[1], G[2], G[3]);
            po4[2 * plane4 + o] = make_float4(B[0], B[1], B[2], B[3]);
        }
    }
}

extern "C" void kernel_launch(void* const* d_in, const int* in_sizes, int n_in,
                              void* d_out, int out_size)
{
    const float* x = (const float*)d_in[0];
    float* out = (float*)d_out;
    (void)in_sizes; (void)n_in; (void)out_size;
    dim3 grid(8, 16, 16);   // tile-col pairs (16/2), tile rows (512/32), batch
    diffjpeg_kernel<<<grid, 256>>>(x, out);
}

// round 15
// speedup vs baseline: 1.1181x; 1.0523x over previous
#include <cuda_runtime.h>

// 8-point DCT-II basis as compile-time constants -> FFMA immediates after unroll.
__device__ constexpr float D8[8][8] = {
  { 0.35355339059327373f, 0.35355339059327373f, 0.35355339059327373f, 0.35355339059327373f,
    0.35355339059327373f, 0.35355339059327373f, 0.35355339059327373f, 0.35355339059327373f},
  { 0.49039264020161522f, 0.41573480615127262f, 0.27778511650980114f, 0.09754516100806417f,
   -0.09754516100806417f,-0.27778511650980114f,-0.41573480615127262f,-0.49039264020161522f},
  { 0.46193976625564337f, 0.19134171618254492f,-0.19134171618254492f,-0.46193976625564337f,
   -0.46193976625564337f,-0.19134171618254492f, 0.19134171618254492f, 0.46193976625564337f},
  { 0.41573480615127262f,-0.09754516100806417f,-0.49039264020161522f,-0.27778511650980114f,
    0.27778511650980114f, 0.49039264020161522f, 0.09754516100806417f,-0.41573480615127262f},
  { 0.35355339059327379f,-0.35355339059327379f,-0.35355339059327379f, 0.35355339059327379f,
    0.35355339059327379f,-0.35355339059327379f,-0.35355339059327379f, 0.35355339059327379f},
  { 0.27778511650980114f,-0.49039264020161522f, 0.09754516100806417f, 0.41573480615127262f,
   -0.41573480615127262f,-0.09754516100806417f, 0.49039264020161522f,-0.27778511650980114f},
  { 0.19134171618254492f,-0.46193976625564337f, 0.46193976625564337f,-0.19134171618254492f,
   -0.19134171618254492f, 0.46193976625564337f,-0.46193976625564337f, 0.19134171618254492f},
  { 0.09754516100806417f,-0.27778511650980114f, 0.41573480615127262f,-0.49039264020161522f,
    0.49039264020161522f,-0.41573480615127262f, 0.27778511650980114f,-0.09754516100806417f}
};

__constant__ float QYc[64] = {
  16,11,10,16,24,40,51,61,
  12,12,14,19,26,58,60,55,
  14,13,16,24,40,57,69,56,
  14,17,22,29,51,87,80,62,
  18,22,37,56,68,109,103,77,
  24,35,55,64,81,104,113,92,
  49,64,78,87,103,121,120,101,
  72,92,95,98,112,100,103,99
};
__constant__ float QCc[64] = {
  17,18,24,47,99,99,99,99,
  18,21,26,66,99,99,99,99,
  24,26,56,99,99,99,99,99,
  47,66,99,99,99,99,99,99,
  99,99,99,99,99,99,99,99,
  99,99,99,99,99,99,99,99,
  99,99,99,99,99,99,99,99,
  99,99,99,99,99,99,99,99
};

#define QFACTOR 0.5f
// 1024 * D8[0][0]: DC offset equivalent of the per-pixel -128 shift.
#define DC_SHIFT 362.03867196751236f

// Forward 8-pt DCT with even/odd fold (all 8 outputs). 8 ADD + 32 FMA.
#define DCT_FWD_FOLD(in8, out8)                                            \
  {                                                                        \
    float e_[4], o_[4];                                                    \
    _Pragma("unroll")                                                      \
    for (int j_ = 0; j_ < 4; ++j_) {                                       \
      e_[j_] = in8[j_] + in8[7 - j_];                                      \
      o_[j_] = in8[j_] - in8[7 - j_];                                      \
    }                                                                      \
    _Pragma("unroll")                                                      \
    for (int v_ = 0; v_ < 8; v_ += 2) {                                    \
      float se_ = 0.f, so_ = 0.f;                                          \
      _Pragma("unroll")                                                    \
      for (int j_ = 0; j_ < 4; ++j_) {                                     \
        se_ += D8[v_][j_] * e_[j_];                                        \
        so_ += D8[v_ + 1][j_] * o_[j_];                                    \
      }                                                                    \
      out8[v_] = se_; out8[v_ + 1] = so_;                                  \
    }                                                                      \
  }

// Inverse 8-pt DCT with fold (all 8 outputs). 32 FMA + 8 ADD.
#define DCT_INV_FOLD(w8, rec8)                                             \
  {                                                                        \
    _Pragma("unroll")                                                      \
    for (int j_ = 0; j_ < 4; ++j_) {                                       \
      float E_ = 0.f, O_ = 0.f;                                            \
      _Pragma("unroll")                                                    \
      for (int v_ = 0; v_ < 8; v_ += 2) {                                  \
        E_ += D8[v_][j_] * w8[v_];                                         \
        O_ += D8[v_ + 1][j_] * w8[v_ + 1];                                 \
      }                                                                    \
      rec8[j_] = E_ + O_; rec8[7 - j_] = E_ - O_;                          \
    }                                                                      \
  }

// Tile: 32 rows x 32 cols, 256 threads, FOUR tiles per CTA (sequential) ->
// grid 1024 CTAs = single wave on 148 SMs at 8 CTAs/SM.
// 24 blocks of 8x8 in shared scratch:
//   blk 0..15 : Y   (blk = (row>>3)*4 + (col>>3))
//   blk 16..19: Cb  (16x16 downsampled), blk 20..23: Cr
// s[blk*72 + x*9 + y]: conflict-free for both access orientations.

__global__ __launch_bounds__(256, 8) void diffjpeg_kernel(
    const float* __restrict__ x, float* __restrict__ out)
{
    __shared__ float s[24 * 72];
    __shared__ float2 qYp[64], qCp[64];   // (q, 1/q)

    const int tid = threadIdx.x;
    if (tid < 64) {
        const float a = QYc[tid] * QFACTOR;
        const float b = QCc[tid] * QFACTOR;
        qYp[tid] = make_float2(a, 1.0f / a);
        qCp[tid] = make_float2(b, 1.0f / b);
    }

    const int bz = blockIdx.z;
    const int tr = blockIdx.y;
    const size_t plane4 = 512 * 512 / 4;
    const float4* pbase = (const float4*)x + (size_t)bz * 3 * plane4 + (size_t)(tr * 32) * 128;
    float4*       obase = (float4*)out     + (size_t)bz * 3 * plane4 + (size_t)(tr * 32) * 128;

    const int row = tid >> 3;   // 0..31
    const int cg  = tid & 7;    // 0..7 -> cols 4cg..4cg+3
    const bool hi = (cg & 1);
    const int yblk = (row >> 3) * 4 + (cg >> 1);
    float* bYv = s + yblk * 72 + (row & 7) * 9;

    #pragma unroll 1
    for (int it = 0; it < 4; ++it) {
        const int tcc = blockIdx.x * 4 + it;       // tile col 0..15
        const float4* px4 = pbase + tcc * 8;
        float4*       po4 = obase + tcc * 8;
        if (it) __syncthreads();   // output phase of prev tile read s

        // ---- Phase 1: load, clip, RGB->YCbCr (folded identity), Y forward-y
        //      DCT (regs+shfl, DC-shift trick), chroma 2x2 downsample ----
        {
            const float4 R4 = px4[(size_t)row * 128 + cg];
            const float4 G4 = px4[plane4 + (size_t)row * 128 + cg];
            const float4 B4 = px4[2 * plane4 + (size_t)row * 128 + cg];
            float rr[4] = {R4.x, R4.y, R4.z, R4.w};
            float gg[4] = {G4.x, G4.y, G4.z, G4.w};
            float bb[4] = {B4.x, B4.y, B4.z, B4.w};
            float yv[4];
            float cbh[2] = {0.f, 0.f}, crh[2] = {0.f, 0.f};
            #pragma unroll
            for (int j = 0; j < 4; ++j) {
                const float r1 = __saturatef(rr[j]);
                const float g1 = __saturatef(gg[j]);
                const float b1 = __saturatef(bb[j]);
                const float y = 76.245f * r1 + 149.685f * g1 + 29.07f * b1;
                yv[j] = y;
                cbh[j >> 1] += fmaf(b1, 255.f, -y);   // (B255 - Y)
                crh[j >> 1] += fmaf(r1, 255.f, -y);   // (R255 - Y)
            }
            float ov[4];
            #pragma unroll
            for (int j = 0; j < 4; ++j) ov[j] = __shfl_xor_sync(0xffffffffu, yv[j], 1);
            float in8[8];
            #pragma unroll
            for (int j = 0; j < 4; ++j) {
                in8[j]     = hi ? ov[j] : yv[j];
                in8[4 + j] = hi ? yv[j] : ov[j];
            }
            float out8[8];
            DCT_FWD_FOLD(in8, out8);
            out8[0] -= DC_SHIFT;   // equivalent of -128 per pixel (v=0 only)
            #pragma unroll
            for (int j = 0; j < 4; ++j)
                bYv[(hi ? 4 : 0) + j] = hi ? out8[4 + j] : out8[j];

            #pragma unroll
            for (int k = 0; k < 2; ++k) {
                cbh[k] += __shfl_xor_sync(0xffffffffu, cbh[k], 8);
                crh[k] += __shfl_xor_sync(0xffffffffu, crh[k], 8);
            }
            if ((row & 1) == 0) {
                const int crow = row >> 1;
                const int base = (crow & 7) * 9;
                #pragma unroll
                for (int k = 0; k < 2; ++k) {
                    const int ccol = 2 * cg + k;
                    const int cblk = 16 + (crow >> 3) * 2 + (ccol >> 3);
                    // 0.25 (avg) * 0.5643341 / 0.7132668 (color identity)
                    s[cblk * 72 + base + (ccol & 7)]       = 0.14108352144469527f * cbh[k];
                    s[(cblk + 4) * 72 + base + (ccol & 7)] = 0.17831669044222540f * crh[k];
                }
            }
        }
        __syncthreads();

        // ---- Region 2: Y pass-B on threads 0..127; chroma chain on 128..255 ----
        if (tid < 128) {
            const int blk = tid >> 3, v = tid & 7;
            float* bp = s + blk * 72 + v;
            float t[8];
            #pragma unroll
            for (int xx = 0; xx < 8; ++xx) t[xx] = bp[xx * 9];
            float cf[8];
            DCT_FWD_FOLD(t, cf);
            #pragma unroll
            for (int u = 0; u < 8; ++u) {
                const float2 qq = qYp[u * 8 + v];
                cf[u] = rintf(cf[u] * qq.y) * qq.x;   // round-half-even
            }
            float w[8];
            DCT_INV_FOLD(cf, w);
            #pragma unroll
            for (int xx = 0; xx < 8; ++xx) bp[xx * 9] = w[xx];
        } else {
            const int u = tid - 128;   // chroma = 8 blocks x 8 = 64 units
            if (u < 64) {
                const int blk = 16 + (u >> 3), xx = u & 7;
                float* bp = s + blk * 72 + xx * 9;
                float in8[8];
                #pragma unroll
                for (int j = 0; j < 8; ++j) in8[j] = bp[j];
                float out8[8];
                DCT_FWD_FOLD(in8, out8);
                #pragma unroll
                for (int j = 0; j < 8; ++j) bp[j] = out8[j];
            }
            asm volatile("bar.sync 1, 128;" ::: "memory");
            if (u < 64) {
                const int blk = 16 + (u >> 3), v = u & 7;
                float* bp = s + blk * 72 + v;
                float t[8];
                #pragma unroll
                for (int xx = 0; xx < 8; ++xx) t[xx] = bp[xx * 9];
                float cf[8];
                DCT_FWD_FOLD(t, cf);
                #pragma unroll
                for (int uu = 0; uu < 8; ++uu) {
                    const float2 qq = qCp[uu * 8 + v];
                    cf[uu] = rintf(cf[uu] * qq.y) * qq.x;
                }
                float w[8];
                DCT_INV_FOLD(cf, w);
                #pragma unroll
                for (int xx = 0; xx < 8; ++xx) bp[xx * 9] = w[xx];
            }
            asm volatile("bar.sync 1, 128;" ::: "memory");
            if (u < 64) {
                const int blk = 16 + (u >> 3), xx = u & 7;
                float* bp = s + blk * 72 + xx * 9;
                float w[8];
                #pragma unroll
                for (int v = 0; v < 8; ++v) w[v] = bp[v];
                float rec[8];
                DCT_INV_FOLD(w, rec);
                #pragma unroll
                for (int j = 0; j < 8; ++j) bp[j] = rec[j];
            }
        }
        __syncthreads();

        // ---- Output: inverse-y for Y in registers (DC-shift restores +128)
        //      + chroma upsample + store ----
        {
            float w[8];
            #pragma unroll
            for (int v = 0; v < 8; ++v) w[v] = bYv[v];
            w[0] += DC_SHIFT;   // adds +128 to every reconstructed pixel
            float E[4], O[4];
            #pragma unroll
            for (int j = 0; j < 4; ++j) {
                float Ee = 0.f, Oo = 0.f;
                #pragma unroll
                for (int v = 0; v < 8; v += 2) {
                    Ee += D8[v][j] * w[v];
                    Oo += D8[v + 1][j] * w[v + 1];
                }
                E[j] = Ee; O[j] = Oo;
            }
            float yrec[4];
            #pragma unroll
            for (int j = 0; j < 4; ++j)
                yrec[j] = hi ? (E[3 - j] - O[3 - j]) : (E[j] + O[j]);

            const int crow = row >> 1;
            const int base = (crow & 7) * 9;
            const int ccol0 = 2 * cg;
            const int cblk = 16 + (crow >> 3) * 2 + (ccol0 >> 3);
            const float cb0 = s[cblk * 72 + base + (ccol0 & 7)];
            const float cb1 = s[cblk * 72 + base + (ccol0 & 7) + 1];
            const float cr0 = s[(cblk + 4) * 72 + base + (ccol0 & 7)];
            const float cr1 = s[(cblk + 4) * 72 + base + (ccol0 & 7) + 1];
            const float cbm[4] = {cb0, cb0, cb1, cb1};
            const float crm[4] = {cr0, cr0, cr1, cr1};
            float R[4], G[4], B[4];
            #pragma unroll
            for (int j = 0; j < 4; ++j) {
                const float yv = yrec[j];
                R[j] = __saturatef((yv + 1.402f * crm[j]) * (1.0f / 255.0f));
                G[j] = __saturatef((yv - 0.344136f * cbm[j] - 0.714136f * crm[j]) * (1.0f / 255.0f));
                B[j] = __saturatef((yv + 1.772f * cbm[j]) * (1.0f / 255.0f));
            }
            const size_t o = (size_t)row * 128 + cg;
            po4[o]              = make_float4(R[0], R[1], R[2], R[3]);
            po4[plane4 + o]     = make_float4(G[0], G[1], G[2], G[3]);
            po4[2 * plane4 + o] = make_float4(B[0], B[1], B[2], B[3]);
        }
    }
}

extern "C" void kernel_launch(void* const* d_in, const int* in_sizes, int n_in,
                              void* d_out, int out_size)
{
    const float* x = (const float*)d_in[0];
    float* out = (float*)d_out;
    (void)in_sizes; (void)n_in; (void)out_size;
    dim3 grid(4, 16, 16);   // tile-col quads (16/4), tile rows (512/32), batch
    diffjpeg_kernel<<<grid, 256>>>(x, out);
}